// round 3
// baseline (speedup 1.0000x reference)
#include <cuda_runtime.h>

// Fixed problem shape constants (validated against in_sizes at launch).
#define NUM_C 32
#define MAX_H 262144   // 64^3 nodes at depth 6

// 32 MB scratch for the transposed feature table: feat[h][c], 128B rows.
__device__ float g_feat[(size_t)MAX_H * NUM_C];

// ---------------------------------------------------------------------------
// Kernel 1: transpose data (C, H) -> g_feat (H, C) via shared-memory tile.
// ---------------------------------------------------------------------------
__global__ void transpose_CH_to_HC(const float* __restrict__ in, int H)
{
    __shared__ float tile[32][33];   // +1 pad to kill bank conflicts

    const int hbase = blockIdx.x * 32;
    const int tx = threadIdx.x;      // 0..31
    const int ty = threadIdx.y;      // 0..7

    // Load: 32 channels x 32 h-values, coalesced over h.
#pragma unroll
    for (int i = 0; i < 32; i += 8) {
        const int c = ty + i;
        const int h = hbase + tx;
        if (h < H)
            tile[c][tx] = in[(size_t)c * H + h];
    }
    __syncthreads();

    // Store: rows of g_feat (128B each), coalesced over c (= tx).
#pragma unroll
    for (int i = 0; i < 32; i += 8) {
        const int hl = ty + i;
        const int h  = hbase + hl;
        if (h < H)
            g_feat[(size_t)h * NUM_C + tx] = tile[tx][hl];
    }
}

// ---------------------------------------------------------------------------
// Kernel 2: trilinear gather. One thread per query point.
// ---------------------------------------------------------------------------
__global__ void __launch_bounds__(256)
octree_trilinear_kernel(const float4* __restrict__ pts,
                        const int*    __restrict__ lut,
                        float*        __restrict__ out,
                        int N, int G)
{
    const int n = blockIdx.x * blockDim.x + threadIdx.x;
    if (n >= N) return;

    const float4 p = pts[n];
    const float xf = p.x - 0.5f;
    const float yf = p.y - 0.5f;
    const float zf = p.z - 0.5f;
    const float xi = floorf(xf);
    const float yi = floorf(yf);
    const float zi = floorf(zf);
    const float fx = xf - xi;
    const float fy = yf - yi;
    const float fz = zf - zi;
    const int ix = (int)xi;
    const int iy = (int)yi;
    const int iz = (int)zi;

    float acc[NUM_C];
#pragma unroll
    for (int c = 0; c < NUM_C; ++c) acc[c] = 0.0f;
    float wsum = 0.0f;

#pragma unroll
    for (int k = 0; k < 8; ++k) {
        const int cx = ix + ((k >> 2) & 1);
        const int cy = iy + ((k >> 1) & 1);
        const int cz = iz + (k & 1);

        const bool inb = ((unsigned)cx < (unsigned)G) &
                         ((unsigned)cy < (unsigned)G) &
                         ((unsigned)cz < (unsigned)G);
        if (inb) {
            const int idx = __ldg(&lut[((size_t)cx * G + cy) * G + cz]);
            if (idx >= 0) {
                const float wx = (k & 4) ? fx : (1.0f - fx);
                const float wy = (k & 2) ? fy : (1.0f - fy);
                const float wz = (k & 1) ? fz : (1.0f - fz);
                const float w = wx * wy * wz;
                wsum += w;

                const float4* __restrict__ f =
                    reinterpret_cast<const float4*>(g_feat + ((size_t)idx * NUM_C));
#pragma unroll
                for (int j = 0; j < NUM_C / 4; ++j) {
                    const float4 v = f[j];
                    acc[4 * j + 0] = fmaf(w, v.x, acc[4 * j + 0]);
                    acc[4 * j + 1] = fmaf(w, v.y, acc[4 * j + 1]);
                    acc[4 * j + 2] = fmaf(w, v.z, acc[4 * j + 2]);
                    acc[4 * j + 3] = fmaf(w, v.w, acc[4 * j + 3]);
                }
            }
        }
    }

    const float inv = 1.0f / (wsum + 1e-10f);

    // out layout is (C, N): channel-strided stores, coalesced across n per warp.
#pragma unroll
    for (int c = 0; c < NUM_C; ++c) {
        out[(size_t)c * N + n] = acc[c] * inv;
    }
}

// ---------------------------------------------------------------------------
// Launch: inputs per metadata order = data (f32), pts (f32), lut (i32), depth.
// Everything derived from in_sizes; graph-capturable (two launches, stream 0).
// ---------------------------------------------------------------------------
extern "C" void kernel_launch(void* const* d_in, const int* in_sizes, int n_in,
                              void* d_out, int out_size)
{
    const float* data = (const float*)d_in[0];
    const float* pts  = (const float*)d_in[1];
    const int*   lut  = (const int*)d_in[2];
    float*       out  = (float*)d_out;

    // Derive G from lut element count (G^3), H from data (C*H with C=32).
    int G = 1;
    while (G * G * G < in_sizes[2]) G <<= 1;
    const int H = in_sizes[0] / NUM_C;
    const int N = in_sizes[1] / 4;

    // Kernel 1: transpose feature table into H-major rows.
    {
        dim3 block(32, 8);
        dim3 grid((H + 31) / 32);
        transpose_CH_to_HC<<<grid, block>>>(data, H);
    }

    // Kernel 2: per-point trilinear gather.
    {
        const int threads = 256;
        const int blocks = (N + threads - 1) / threads;
        octree_trilinear_kernel<<<blocks, threads>>>(
            (const float4*)pts, lut, out, N, G);
    }
}

// round 4
// speedup vs baseline: 1.5193x; 1.5193x over previous
#include <cuda_runtime.h>
#include <cuda_fp16.h>

#define NUM_C 32
#define MAX_H 262144   // 64^3 nodes at depth 6

// 16 MB scratch: transposed fp16 feature table feat[h][c], 64B rows.
__device__ __half g_feat_h[(size_t)MAX_H * NUM_C];

// ---------------------------------------------------------------------------
// Kernel 1: transpose + convert data (C, H) f32 -> g_feat_h (H, C) fp16.
// ---------------------------------------------------------------------------
__global__ void transpose_CH_to_HC_half(const float* __restrict__ in, int H)
{
    __shared__ float tile[32][33];

    const int hbase = blockIdx.x * 32;
    const int tx = threadIdx.x;      // 0..31
    const int ty = threadIdx.y;      // 0..7

#pragma unroll
    for (int i = 0; i < 32; i += 8) {
        const int c = ty + i;
        const int h = hbase + tx;
        if (h < H)
            tile[c][tx] = in[(size_t)c * H + h];
    }
    __syncthreads();

#pragma unroll
    for (int i = 0; i < 32; i += 8) {
        const int hl = ty + i;
        const int h  = hbase + hl;
        if (h < H)
            g_feat_h[(size_t)h * NUM_C + tx] = __float2half(tile[tx][hl]);
    }
}

// ---------------------------------------------------------------------------
// Kernel 2: cooperative trilinear gather.
//   8 lanes per point (lane j = corner j). 4 points per warp, 32 per block.
//   Each corner-loop iteration: one warp-wide LDG.64 covers 4 rows (4 lines)
//   instead of 32 -> 8x fewer L1tex wavefronts than one-thread-per-point.
// ---------------------------------------------------------------------------
__global__ void __launch_bounds__(256)
octree_trilinear_coop(const float4* __restrict__ pts,
                      const int*    __restrict__ lut,
                      float*        __restrict__ out,
                      int N, int G)
{
    __shared__ float sm[32 * 33];    // 32 points x 32 channels, padded rows

    const int tid    = threadIdx.x;
    const int warpId = tid >> 5;
    const int lane   = tid & 31;
    const int g      = lane >> 3;    // point-in-warp 0..3
    const int j      = lane & 7;     // corner id 0..7

    const int n0     = blockIdx.x * 32;           // first point of block
    const int pLocal = warpId * 4 + g;            // point-in-block 0..31
    const int p      = n0 + pLocal;
    const int pc     = (p < N) ? p : (N - 1);     // clamped for loads

    // --- per-point geometry (computed redundantly by all 8 lanes of group) ---
    const float4 q = pts[pc];
    const float xf = q.x - 0.5f, yf = q.y - 0.5f, zf = q.z - 0.5f;
    const float xi = floorf(xf), yi = floorf(yf), zi = floorf(zf);
    const float fx = xf - xi, fy = yf - yi, fz = zf - zi;
    const int ix = (int)xi, iy = (int)yi, iz = (int)zi;

    // --- lane j owns corner j: weight + lut index + validity ---
    const int cx = ix + ((j >> 2) & 1);
    const int cy = iy + ((j >> 1) & 1);
    const int cz = iz + (j & 1);
    const bool inb = ((unsigned)cx < (unsigned)G) &
                     ((unsigned)cy < (unsigned)G) &
                     ((unsigned)cz < (unsigned)G);
    int   idx = -1;
    if (inb) idx = __ldg(&lut[((size_t)cx * G + cy) * G + cz]);

    float w = 0.0f;
    if (idx >= 0) {
        const float wx = (j & 4) ? fx : (1.0f - fx);
        const float wy = (j & 2) ? fy : (1.0f - fy);
        const float wz = (j & 1) ? fz : (1.0f - fz);
        w = wx * wy * wz;
    } else {
        idx = 0;
    }

    // --- wsum: reduce w across the 8-lane group ---
    float wsum = w;
#pragma unroll
    for (int off = 4; off > 0; off >>= 1)
        wsum += __shfl_xor_sync(0xffffffffu, wsum, off, 8);

    // --- gather loop: iterate corners; lane j loads chunk j of the row ---
    const uint2* __restrict__ feat8 =
        reinterpret_cast<const uint2*>(g_feat_h);   // 8B = 4 halves per elem

    float4 acc = make_float4(0.f, 0.f, 0.f, 0.f);
#pragma unroll
    for (int k = 0; k < 8; ++k) {
        const float wk  = __shfl_sync(0xffffffffu, w,   k, 8);
        const int   rk  = __shfl_sync(0xffffffffu, idx, k, 8);
        if (wk > 0.0f) {
            uint2 v = __ldg(&feat8[(size_t)rk * 8 + j]);
            const __half2 h0 = *reinterpret_cast<const __half2*>(&v.x);
            const __half2 h1 = *reinterpret_cast<const __half2*>(&v.y);
            const float2 f0 = __half22float2(h0);
            const float2 f1 = __half22float2(h1);
            acc.x = fmaf(wk, f0.x, acc.x);
            acc.y = fmaf(wk, f0.y, acc.y);
            acc.z = fmaf(wk, f1.x, acc.z);
            acc.w = fmaf(wk, f1.y, acc.w);
        }
    }

    const float inv = 1.0f / (wsum + 1e-10f);
    acc.x *= inv; acc.y *= inv; acc.z *= inv; acc.w *= inv;

    // --- stage in smem: sm[point][channel], padded rows (conflict-free) ---
    float* row = sm + pLocal * 33 + 4 * j;
    row[0] = acc.x; row[1] = acc.y; row[2] = acc.z; row[3] = acc.w;
    __syncthreads();

    // --- coalesced (C, N) store: each warp stores one channel x 32 points ---
#pragma unroll
    for (int r = 0; r < 4; ++r) {
        const int e = r * 256 + tid;       // 0..1023
        const int c = e >> 5;              // channel (uniform per warp)
        const int i = e & 31;              // point-in-block (lane-contiguous)
        if (n0 + i < N)
            out[(size_t)c * N + (n0 + i)] = sm[i * 33 + c];
    }
}

// ---------------------------------------------------------------------------
// Launch. Inputs: data (f32), pts (f32), lut (i32), depth.
// ---------------------------------------------------------------------------
extern "C" void kernel_launch(void* const* d_in, const int* in_sizes, int n_in,
                              void* d_out, int out_size)
{
    const float* data = (const float*)d_in[0];
    const float* pts  = (const float*)d_in[1];
    const int*   lut  = (const int*)d_in[2];
    float*       out  = (float*)d_out;

    int G = 1;
    while (G * G * G < in_sizes[2]) G <<= 1;
    const int H = in_sizes[0] / NUM_C;
    const int N = in_sizes[1] / 4;

    {
        dim3 block(32, 8);
        dim3 grid((H + 31) / 32);
        transpose_CH_to_HC_half<<<grid, block>>>(data, H);
    }
    {
        const int blocks = (N + 31) / 32;   // 32 points per 256-thread block
        octree_trilinear_coop<<<blocks, 256>>>(
            (const float4*)pts, lut, out, N, G);
    }
}

// round 5
// speedup vs baseline: 1.5611x; 1.0275x over previous
#include <cuda_runtime.h>
#include <cuda_fp16.h>

#define NUM_C 32
#define MAX_H 262144   // 64^3 nodes at depth 6

// 16 MB scratch: transposed fp16 feature table feat[h][c], 64B rows.
__device__ __half g_feat_h[(size_t)MAX_H * NUM_C];

// ---------------------------------------------------------------------------
// Kernel 1: transpose + convert data (C, H) f32 -> g_feat_h (H, C) fp16.
// ---------------------------------------------------------------------------
__global__ void transpose_CH_to_HC_half(const float* __restrict__ in, int H)
{
    __shared__ float tile[32][33];

    const int hbase = blockIdx.x * 32;
    const int tx = threadIdx.x;      // 0..31
    const int ty = threadIdx.y;      // 0..7

#pragma unroll
    for (int i = 0; i < 32; i += 8) {
        const int c = ty + i;
        const int h = hbase + tx;
        if (h < H)
            tile[c][tx] = in[(size_t)c * H + h];
    }
    __syncthreads();

#pragma unroll
    for (int i = 0; i < 32; i += 8) {
        const int hl = ty + i;
        const int h  = hbase + hl;
        if (h < H)
            g_feat_h[(size_t)h * NUM_C + tx] = __float2half(tile[tx][hl]);
    }
}

// ---------------------------------------------------------------------------
// Kernel 2: cooperative trilinear gather, software-pipelined.
//   8 lanes per point (lane j = corner j), 4 points/warp, 32 per block.
//   Phase 1: broadcast all 8 (w, idx) pairs.
//   Phase 2: issue ALL 8 gather loads back-to-back (MLP = 8).
//   Phase 3: convert + accumulate.
// ---------------------------------------------------------------------------
__global__ void __launch_bounds__(256)
octree_trilinear_coop(const float4* __restrict__ pts,
                      const int*    __restrict__ lut,
                      float*        __restrict__ out,
                      int N, int G)
{
    __shared__ float sm[32 * 33];    // 32 points x 32 channels, padded rows

    const int tid    = threadIdx.x;
    const int warpId = tid >> 5;
    const int lane   = tid & 31;
    const int g      = lane >> 3;    // point-in-warp 0..3
    const int j      = lane & 7;     // corner id 0..7

    const int n0     = blockIdx.x * 32;           // first point of block
    const int pLocal = warpId * 4 + g;            // point-in-block 0..31
    const int p      = n0 + pLocal;
    const int pc     = (p < N) ? p : (N - 1);     // clamped for loads

    // --- per-point geometry (redundant across the 8 lanes of a group) ---
    const float4 q = pts[pc];
    const float xf = q.x - 0.5f, yf = q.y - 0.5f, zf = q.z - 0.5f;
    const float xi = floorf(xf), yi = floorf(yf), zi = floorf(zf);
    const float fx = xf - xi, fy = yf - yi, fz = zf - zi;
    const int ix = (int)xi, iy = (int)yi, iz = (int)zi;

    // --- lane j owns corner j: lut index + weight ---
    const int cx = ix + ((j >> 2) & 1);
    const int cy = iy + ((j >> 1) & 1);
    const int cz = iz + (j & 1);
    const bool inb = ((unsigned)cx < (unsigned)G) &
                     ((unsigned)cy < (unsigned)G) &
                     ((unsigned)cz < (unsigned)G);
    int idx = -1;
    if (inb) idx = __ldg(&lut[((size_t)cx * G + cy) * G + cz]);

    float w = 0.0f;
    if (idx >= 0) {
        const float wx = (j & 4) ? fx : (1.0f - fx);
        const float wy = (j & 2) ? fy : (1.0f - fy);
        const float wz = (j & 1) ? fz : (1.0f - fz);
        w = wx * wy * wz;
    } else {
        idx = 0;
    }

    // --- Phase 1: broadcast all 8 (w, idx) to every lane of the group ---
    float wk[8];
    int   rk[8];
#pragma unroll
    for (int k = 0; k < 8; ++k) {
        wk[k] = __shfl_sync(0xffffffffu, w,   k, 8);
        rk[k] = __shfl_sync(0xffffffffu, idx, k, 8);
    }

    // wsum from the broadcast copies (no extra shuffles needed)
    float wsum = 0.0f;
#pragma unroll
    for (int k = 0; k < 8; ++k) wsum += wk[k];

    // --- Phase 2: issue all 8 gather loads back-to-back (MLP = 8) ---
    const uint2* __restrict__ feat8 =
        reinterpret_cast<const uint2*>(g_feat_h);   // 8B = 4 halves per elem

    uint2 v[8];
#pragma unroll
    for (int k = 0; k < 8; ++k) {
        v[k] = make_uint2(0u, 0u);
        if (wk[k] > 0.0f)
            v[k] = __ldg(&feat8[(size_t)rk[k] * 8 + j]);
    }

    // --- Phase 3: convert + accumulate in fp32 ---
    float4 acc = make_float4(0.f, 0.f, 0.f, 0.f);
#pragma unroll
    for (int k = 0; k < 8; ++k) {
        const __half2 h0 = *reinterpret_cast<const __half2*>(&v[k].x);
        const __half2 h1 = *reinterpret_cast<const __half2*>(&v[k].y);
        const float2 f0 = __half22float2(h0);
        const float2 f1 = __half22float2(h1);
        acc.x = fmaf(wk[k], f0.x, acc.x);
        acc.y = fmaf(wk[k], f0.y, acc.y);
        acc.z = fmaf(wk[k], f1.x, acc.z);
        acc.w = fmaf(wk[k], f1.y, acc.w);
    }

    const float inv = 1.0f / (wsum + 1e-10f);
    acc.x *= inv; acc.y *= inv; acc.z *= inv; acc.w *= inv;

    // --- stage in smem: sm[point][channel], padded rows (conflict-free) ---
    float* row = sm + pLocal * 33 + 4 * j;
    row[0] = acc.x; row[1] = acc.y; row[2] = acc.z; row[3] = acc.w;
    __syncthreads();

    // --- coalesced (C, N) store: each warp stores one channel x 32 points ---
#pragma unroll
    for (int r = 0; r < 4; ++r) {
        const int e = r * 256 + tid;       // 0..1023
        const int c = e >> 5;              // channel (uniform per warp)
        const int i = e & 31;              // point-in-block (lane-contiguous)
        if (n0 + i < N)
            out[(size_t)c * N + (n0 + i)] = sm[i * 33 + c];
    }
}

// ---------------------------------------------------------------------------
// Launch. Inputs: data (f32), pts (f32), lut (i32), depth.
// ---------------------------------------------------------------------------
extern "C" void kernel_launch(void* const* d_in, const int* in_sizes, int n_in,
                              void* d_out, int out_size)
{
    const float* data = (const float*)d_in[0];
    const float* pts  = (const float*)d_in[1];
    const int*   lut  = (const int*)d_in[2];
    float*       out  = (float*)d_out;

    int G = 1;
    while (G * G * G < in_sizes[2]) G <<= 1;
    const int H = in_sizes[0] / NUM_C;
    const int N = in_sizes[1] / 4;

    {
        dim3 block(32, 8);
        dim3 grid((H + 31) / 32);
        transpose_CH_to_HC_half<<<grid, block>>>(data, H);
    }
    {
        const int blocks = (N + 31) / 32;   // 32 points per 256-thread block
        octree_trilinear_coop<<<blocks, 256>>>(
            (const float4*)pts, lut, out, N, G);
    }
}

// round 6
// speedup vs baseline: 1.8644x; 1.1943x over previous
#include <cuda_runtime.h>
#include <cuda_fp16.h>

#define NUM_C 32
#define MAX_H 262144   // 64^3 nodes at depth 6

// 16 MB scratch: transposed fp16 feature table feat[h][c], 64B rows, 16B-aligned.
__device__ __align__(16) __half g_feat_h[(size_t)MAX_H * NUM_C];

// ---------------------------------------------------------------------------
// Kernel 1: transpose + convert data (C, H) f32 -> g_feat_h (H, C) fp16.
// ---------------------------------------------------------------------------
__global__ void transpose_CH_to_HC_half(const float* __restrict__ in, int H)
{
    __shared__ float tile[32][33];

    const int hbase = blockIdx.x * 32;
    const int tx = threadIdx.x;      // 0..31
    const int ty = threadIdx.y;      // 0..7

#pragma unroll
    for (int i = 0; i < 32; i += 8) {
        const int c = ty + i;
        const int h = hbase + tx;
        if (h < H)
            tile[c][tx] = in[(size_t)c * H + h];
    }
    __syncthreads();

#pragma unroll
    for (int i = 0; i < 32; i += 8) {
        const int hl = ty + i;
        const int h  = hbase + hl;
        if (h < H)
            g_feat_h[(size_t)h * NUM_C + tx] = __float2half(tile[tx][hl]);
    }
}

// ---------------------------------------------------------------------------
// Kernel 2: cooperative gather, 4 lanes/point, 8 points/warp, 64 pts/block.
//   Lane j owns corners {j, j+4} (x-pair: lut z-pairs coalesce in-instruction)
//   and the 16B chunk j of every gathered 64B feature row.
// ---------------------------------------------------------------------------
__global__ void __launch_bounds__(256)
octree_trilinear_coop4(const float4* __restrict__ pts,
                       const int*    __restrict__ lut,
                       float*        __restrict__ out,
                       int N, int G)
{
    __shared__ float sm[64 * 33];    // 64 points x 32 channels, pad 33 (odd)

    const int tid    = threadIdx.x;
    const int warpId = tid >> 5;
    const int lane   = tid & 31;
    const int g      = lane >> 2;    // point-in-warp 0..7
    const int j      = lane & 3;     // chunk / corner-pair id 0..3

    const int n0     = blockIdx.x * 64;
    const int pLocal = warpId * 8 + g;            // 0..63
    const int p      = n0 + pLocal;
    const int pc     = (p < N) ? p : (N - 1);

    // --- geometry (4x redundant per point) ---
    const float4 q = pts[pc];
    const float xf = q.x - 0.5f, yf = q.y - 0.5f, zf = q.z - 0.5f;
    const float xi = floorf(xf), yi = floorf(yf), zi = floorf(zf);
    const float fx = xf - xi, fy = yf - yi, fz = zf - zi;
    const int ix = (int)xi, iy = (int)yi, iz = (int)zi;

    // --- lane j: corners j (x=0) and j+4 (x=1); shared (cy, cz) ---
    const int cy  = iy + ((j >> 1) & 1);
    const int cz  = iz + (j & 1);
    const int cxa = ix;
    const int cxb = ix + 1;
    const bool okyz = ((unsigned)cy < (unsigned)G) & ((unsigned)cz < (unsigned)G);

    int idxa = -1, idxb = -1;
    const int yz = cy * G + cz;
    if (okyz & ((unsigned)cxa < (unsigned)G)) idxa = __ldg(&lut[(size_t)cxa * G * G + yz]);
    if (okyz & ((unsigned)cxb < (unsigned)G)) idxb = __ldg(&lut[(size_t)cxb * G * G + yz]);

    const float wyz = ((j & 2) ? fy : (1.0f - fy)) * ((j & 1) ? fz : (1.0f - fz));
    float wa = 0.0f, wb = 0.0f;
    if (idxa >= 0) wa = (1.0f - fx) * wyz; else idxa = 0;
    if (idxb >= 0) wb = fx * wyz;          else idxb = 0;

    // --- broadcast all 8 (w, idx) across the 4-lane group ---
    float wk[8];
    int   rk[8];
#pragma unroll
    for (int k = 0; k < 4; ++k) {
        wk[k]     = __shfl_sync(0xffffffffu, wa,   k, 4);
        wk[k + 4] = __shfl_sync(0xffffffffu, wb,   k, 4);
        rk[k]     = __shfl_sync(0xffffffffu, idxa, k, 4);
        rk[k + 4] = __shfl_sync(0xffffffffu, idxb, k, 4);
    }

    float wsum = 0.0f;
#pragma unroll
    for (int k = 0; k < 8; ++k) wsum += wk[k];

    // --- gather: unconditional LDG.128, software-pipelined (window ~5) ---
    const uint4* __restrict__ feat16 = reinterpret_cast<const uint4*>(g_feat_h);

    float acc[8];
#pragma unroll
    for (int t = 0; t < 8; ++t) acc[t] = 0.0f;

#define LDROW(k) __ldg(&feat16[(size_t)rk[k] * 4 + j])
#define CONSUME(v, w)                                                    \
    do {                                                                 \
        const __half2* hp = reinterpret_cast<const __half2*>(&(v));      \
        _Pragma("unroll")                                                \
        for (int t = 0; t < 4; ++t) {                                    \
            const float2 f = __half22float2(hp[t]);                      \
            acc[2 * t]     = fmaf((w), f.x, acc[2 * t]);                 \
            acc[2 * t + 1] = fmaf((w), f.y, acc[2 * t + 1]);             \
        }                                                                \
    } while (0)

    uint4 v0 = LDROW(0);
    uint4 v1 = LDROW(1);
    uint4 v2 = LDROW(2);
    uint4 v3 = LDROW(3);
    uint4 v4 = LDROW(4); CONSUME(v0, wk[0]);
    uint4 v5 = LDROW(5); CONSUME(v1, wk[1]);
    uint4 v6 = LDROW(6); CONSUME(v2, wk[2]);
    uint4 v7 = LDROW(7); CONSUME(v3, wk[3]);
    CONSUME(v4, wk[4]);
    CONSUME(v5, wk[5]);
    CONSUME(v6, wk[6]);
    CONSUME(v7, wk[7]);
#undef LDROW
#undef CONSUME

    const float inv = 1.0f / (wsum + 1e-10f);

    // --- stage: sm[point][channel]; lane j holds channels 8j..8j+7 ---
    // bank of sm[pLocal*33 + 8j + t] = (g + 8j + t') distinct across warp: OK
    float* row = sm + pLocal * 33 + 8 * j;
#pragma unroll
    for (int t = 0; t < 8; ++t) row[t] = acc[t] * inv;
    __syncthreads();

    // --- coalesced (C, N) store: warp = one channel x 32 consecutive points ---
#pragma unroll
    for (int r = 0; r < 8; ++r) {
        const int e = r * 256 + tid;       // 0..2047
        const int c = e >> 6;              // channel (uniform per warp)
        const int i = e & 63;              // point-in-block (lane-contiguous)
        if (n0 + i < N)
            out[(size_t)c * N + (n0 + i)] = sm[i * 33 + c];
    }
}

// ---------------------------------------------------------------------------
// Launch. Inputs: data (f32), pts (f32), lut (i32), depth.
// ---------------------------------------------------------------------------
extern "C" void kernel_launch(void* const* d_in, const int* in_sizes, int n_in,
                              void* d_out, int out_size)
{
    const float* data = (const float*)d_in[0];
    const float* pts  = (const float*)d_in[1];
    const int*   lut  = (const int*)d_in[2];
    float*       out  = (float*)d_out;

    int G = 1;
    while (G * G * G < in_sizes[2]) G <<= 1;
    const int H = in_sizes[0] / NUM_C;
    const int N = in_sizes[1] / 4;

    {
        dim3 block(32, 8);
        dim3 grid((H + 31) / 32);
        transpose_CH_to_HC_half<<<grid, block>>>(data, H);
    }
    {
        const int blocks = (N + 63) / 64;   // 64 points per 256-thread block
        octree_trilinear_coop4<<<blocks, 256>>>(
            (const float4*)pts, lut, out, N, G);
    }
}

// round 7
// speedup vs baseline: 2.7137x; 1.4555x over previous
#include <cuda_runtime.h>
#include <cuda_fp16.h>

#define NUM_C 32
#define MAX_H 262144   // 64^3 nodes at depth 6
#define MAX_G 64
#define MAX_GG (MAX_G + 1)   // base-cell coord range [-1, G-1] -> 65 values

// 16 MB scratch: transposed fp16 feature table feat[h][c], 64B rows.
__device__ __align__(16) __half g_feat_h[(size_t)MAX_H * NUM_C];
// 8.8 MB packed cell table: 8 corner indices per base cell, 32B rows.
__device__ __align__(16) int g_cell[(size_t)MAX_GG * MAX_GG * MAX_GG * 8];

// ---------------------------------------------------------------------------
// Kernel 1a: transpose + convert data (C, H) f32 -> g_feat_h (H, C) fp16.
// ---------------------------------------------------------------------------
__global__ void transpose_CH_to_HC_half(const float* __restrict__ in, int H)
{
    __shared__ float tile[32][33];

    const int hbase = blockIdx.x * 32;
    const int tx = threadIdx.x;      // 0..31
    const int ty = threadIdx.y;      // 0..7

#pragma unroll
    for (int i = 0; i < 32; i += 8) {
        const int c = ty + i;
        const int h = hbase + tx;
        if (h < H)
            tile[c][tx] = in[(size_t)c * H + h];
    }
    __syncthreads();

#pragma unroll
    for (int i = 0; i < 32; i += 8) {
        const int hl = ty + i;
        const int h  = hbase + hl;
        if (h < H)
            g_feat_h[(size_t)h * NUM_C + tx] = __float2half(tile[tx][hl]);
    }
}

// ---------------------------------------------------------------------------
// Kernel 1b: build packed cell table. One thread per base cell (ix,iy,iz)
// in [-1, G-1]^3; stores the 8 corner lut values (bounds -> -1), 32B row.
// Corner k = (kx<<2)|(ky<<1)|kz.
// ---------------------------------------------------------------------------
__global__ void build_cell_lut(const int* __restrict__ lut, int G)
{
    const int GG = G + 1;
    const int total = GG * GG * GG;
    const int cid = blockIdx.x * blockDim.x + threadIdx.x;
    if (cid >= total) return;

    const int bz = cid % GG - 1;
    const int by = (cid / GG) % GG - 1;
    const int bx = cid / (GG * GG) - 1;

    int v[8];
#pragma unroll
    for (int k = 0; k < 8; ++k) {
        const int cx = bx + ((k >> 2) & 1);
        const int cy = by + ((k >> 1) & 1);
        const int cz = bz + (k & 1);
        int idx = -1;
        if (((unsigned)cx < (unsigned)G) & ((unsigned)cy < (unsigned)G) &
            ((unsigned)cz < (unsigned)G))
            idx = __ldg(&lut[((size_t)cx * G + cy) * G + cz]);
        v[k] = idx;
    }

    int4* dst = reinterpret_cast<int4*>(&g_cell[(size_t)cid * 8]);
    dst[0] = make_int4(v[0], v[1], v[2], v[3]);
    dst[1] = make_int4(v[4], v[5], v[6], v[7]);
}

// ---------------------------------------------------------------------------
// Kernel 2: cooperative gather, 4 lanes/point, 8 points/warp, 64 pts/block.
//   Lane j owns corner pair {2j, 2j+1} (z-pair) via ONE 8B load from the
//   packed cell row (1 L1 line per point, vs 4 from the raw lut), and the
//   16B chunk j of every gathered 64B feature row.
// ---------------------------------------------------------------------------
__global__ void __launch_bounds__(256)
octree_trilinear_coop4(const float4* __restrict__ pts,
                       float*        __restrict__ out,
                       int N, int G)
{
    __shared__ float sm[64 * 33];    // 64 points x 32 channels, pad 33 (odd)

    const int tid    = threadIdx.x;
    const int warpId = tid >> 5;
    const int lane   = tid & 31;
    const int g      = lane >> 2;    // point-in-warp 0..7
    const int j      = lane & 3;     // chunk / corner-pair id 0..3

    const int n0     = blockIdx.x * 64;
    const int pLocal = warpId * 8 + g;            // 0..63
    const int p      = n0 + pLocal;
    const int pc     = (p < N) ? p : (N - 1);

    // --- geometry (4x redundant per point) ---
    const float4 q = pts[pc];
    const float xf = q.x - 0.5f, yf = q.y - 0.5f, zf = q.z - 0.5f;
    const float xi = floorf(xf), yi = floorf(yf), zi = floorf(zf);
    const float fx = xf - xi, fy = yf - yi, fz = zf - zi;
    const int GG = G + 1;
    const int ix = min(max((int)xi, -1), G - 1);
    const int iy = min(max((int)yi, -1), G - 1);
    const int iz = min(max((int)zi, -1), G - 1);

    // --- one 8B load: corners 2j (kz=0) and 2j+1 (kz=1); kx=j>>1, ky=j&1 ---
    const int cid = ((ix + 1) * GG + (iy + 1)) * GG + (iz + 1);
    const int2 pr = __ldg(&reinterpret_cast<const int2*>(g_cell)[(size_t)cid * 4 + j]);
    int idxa = pr.x, idxb = pr.y;

    const float wxy = ((j & 2) ? fx : (1.0f - fx)) * ((j & 1) ? fy : (1.0f - fy));
    float wa = 0.0f, wb = 0.0f;
    if (idxa >= 0) wa = wxy * (1.0f - fz); else idxa = 0;
    if (idxb >= 0) wb = wxy * fz;          else idxb = 0;

    // --- broadcast all 8 (w, idx) across the 4-lane group ---
    float wk[8];
    int   rk[8];
#pragma unroll
    for (int k = 0; k < 4; ++k) {
        wk[2 * k]     = __shfl_sync(0xffffffffu, wa,   k, 4);
        wk[2 * k + 1] = __shfl_sync(0xffffffffu, wb,   k, 4);
        rk[2 * k]     = __shfl_sync(0xffffffffu, idxa, k, 4);
        rk[2 * k + 1] = __shfl_sync(0xffffffffu, idxb, k, 4);
    }

    float wsum = 0.0f;
#pragma unroll
    for (int k = 0; k < 8; ++k) wsum += wk[k];

    // --- gather: unconditional LDG.128, software-pipelined ---
    const uint4* __restrict__ feat16 = reinterpret_cast<const uint4*>(g_feat_h);

    float acc[8];
#pragma unroll
    for (int t = 0; t < 8; ++t) acc[t] = 0.0f;

#define LDROW(k) __ldg(&feat16[(size_t)rk[k] * 4 + j])
#define CONSUME(v, w)                                                    \
    do {                                                                 \
        const __half2* hp = reinterpret_cast<const __half2*>(&(v));      \
        _Pragma("unroll")                                                \
        for (int t = 0; t < 4; ++t) {                                    \
            const float2 f = __half22float2(hp[t]);                      \
            acc[2 * t]     = fmaf((w), f.x, acc[2 * t]);                 \
            acc[2 * t + 1] = fmaf((w), f.y, acc[2 * t + 1]);             \
        }                                                                \
    } while (0)

    uint4 v0 = LDROW(0);
    uint4 v1 = LDROW(1);
    uint4 v2 = LDROW(2);
    uint4 v3 = LDROW(3);
    uint4 v4 = LDROW(4); CONSUME(v0, wk[0]);
    uint4 v5 = LDROW(5); CONSUME(v1, wk[1]);
    uint4 v6 = LDROW(6); CONSUME(v2, wk[2]);
    uint4 v7 = LDROW(7); CONSUME(v3, wk[3]);
    CONSUME(v4, wk[4]);
    CONSUME(v5, wk[5]);
    CONSUME(v6, wk[6]);
    CONSUME(v7, wk[7]);
#undef LDROW
#undef CONSUME

    const float inv = 1.0f / (wsum + 1e-10f);

    // --- stage: sm[point][channel]; lane j holds channels 8j..8j+7 ---
    float* row = sm + pLocal * 33 + 8 * j;
#pragma unroll
    for (int t = 0; t < 8; ++t) row[t] = acc[t] * inv;
    __syncthreads();

    // --- coalesced (C, N) store: warp = one channel x 32 consecutive points ---
#pragma unroll
    for (int r = 0; r < 8; ++r) {
        const int e = r * 256 + tid;       // 0..2047
        const int c = e >> 6;              // channel (uniform per warp)
        const int i = e & 63;              // point-in-block (lane-contiguous)
        if (n0 + i < N)
            out[(size_t)c * N + (n0 + i)] = sm[i * 33 + c];
    }
}

// ---------------------------------------------------------------------------
// Launch. Inputs: data (f32), pts (f32), lut (i32), depth.
// ---------------------------------------------------------------------------
extern "C" void kernel_launch(void* const* d_in, const int* in_sizes, int n_in,
                              void* d_out, int out_size)
{
    const float* data = (const float*)d_in[0];
    const float* pts  = (const float*)d_in[1];
    const int*   lut  = (const int*)d_in[2];
    float*       out  = (float*)d_out;

    int G = 1;
    while (G * G * G < in_sizes[2]) G <<= 1;
    const int H = in_sizes[0] / NUM_C;
    const int N = in_sizes[1] / 4;

    {
        dim3 block(32, 8);
        dim3 grid((H + 31) / 32);
        transpose_CH_to_HC_half<<<grid, block>>>(data, H);
    }
    {
        const int GG = G + 1;
        const int total = GG * GG * GG;
        build_cell_lut<<<(total + 255) / 256, 256>>>(lut, G);
    }
    {
        const int blocks = (N + 63) / 64;   // 64 points per 256-thread block
        octree_trilinear_coop4<<<blocks, 256>>>(
            (const float4*)pts, out, N, G);
    }
}

// round 8
// speedup vs baseline: 2.8312x; 1.0433x over previous
#include <cuda_runtime.h>
#include <cuda_fp16.h>

#define NUM_C 32
#define MAX_H 262144   // 64^3 nodes at depth 6
#define MAX_G 64
#define MAX_GG (MAX_G + 1)   // base-cell coord range [-1, G-1] -> 65 values

// 16 MB: transposed fp16 feature table, 64B rows, channel-PERMUTED within row:
//   row position pos = j*8 + t  holds channel c = (t&1) | (j<<1) | ((t>>1)<<3)
// so 16B chunk j carries channels {2j, 2j+1, 2j+8, 2j+9, 2j+16, ..., 2j+25}
// as half2 pairs of CONSECUTIVE channels (2j+8u, 2j+8u+1).
__device__ __align__(16) __half g_feat_h[(size_t)MAX_H * NUM_C];
// 8.8 MB packed cell table: 8 corner indices per base cell, 32B rows.
__device__ __align__(16) int g_cell[(size_t)MAX_GG * MAX_GG * MAX_GG * 8];

// ---------------------------------------------------------------------------
// Kernel 1 (fused prep): blocks [0, nTrans) transpose+convert data (C,H) f32
// -> g_feat_h (H, C-permuted) fp16; blocks [nTrans, ...) build the packed
// cell table. The two halves are independent and overlap on the chip.
// ---------------------------------------------------------------------------
__global__ void __launch_bounds__(256)
prep_kernel(const float* __restrict__ data, const int* __restrict__ lut,
            int H, int G, int nTrans)
{
    if ((int)blockIdx.x < nTrans) {
        // ---- transpose + fp16 convert, 32c x 64h tile ----
        __shared__ float tile[32][65];
        const int tid = threadIdx.x;
        const int tx = tid & 31;
        const int ty = tid >> 5;
        const int hbase = blockIdx.x * 64;

#pragma unroll
        for (int i = 0; i < 4; ++i) {
            const int c = ty + 8 * i;
            const int h = hbase + 2 * tx;
            if (h + 1 < H) {
                const float2 v =
                    *reinterpret_cast<const float2*>(&data[(size_t)c * H + h]);
                tile[c][2 * tx]     = v.x;
                tile[c][2 * tx + 1] = v.y;
            } else if (h < H) {
                tile[c][2 * tx] = data[(size_t)c * H + h];
            }
        }
        __syncthreads();

        __half2* outh2 = reinterpret_cast<__half2*>(g_feat_h);
#pragma unroll
        for (int r = 0; r < 4; ++r) {
            const int e   = r * 256 + tid;
            const int row = e >> 4;           // 0..63 (h within tile)
            const int q   = e & 15;           // half2 slot within 64B row
            const int h   = hbase + row;
            if (h < H) {
                // channels for row positions 2q, 2q+1 under the permutation
                const int c0 = ((q >> 2) << 1) | ((q & 3) << 3);
                const int c1 = c0 | 1;
                outh2[(size_t)h * 16 + q] =
                    __floats2half2_rn(tile[c0][row], tile[c1][row]);
            }
        }
    } else {
        // ---- packed cell table: one thread per base cell in [-1, G-1]^3 ----
        const int GG = G + 1;
        const int total = GG * GG * GG;
        const int cid = (blockIdx.x - nTrans) * blockDim.x + threadIdx.x;
        if (cid >= total) return;

        const int bz = cid % GG - 1;
        const int by = (cid / GG) % GG - 1;
        const int bx = cid / (GG * GG) - 1;

        int v[8];
#pragma unroll
        for (int k = 0; k < 8; ++k) {
            const int cx = bx + ((k >> 2) & 1);
            const int cy = by + ((k >> 1) & 1);
            const int cz = bz + (k & 1);
            int idx = -1;
            if (((unsigned)cx < (unsigned)G) & ((unsigned)cy < (unsigned)G) &
                ((unsigned)cz < (unsigned)G))
                idx = __ldg(&lut[((size_t)cx * G + cy) * G + cz]);
            v[k] = idx;
        }
        int4* dst = reinterpret_cast<int4*>(&g_cell[(size_t)cid * 8]);
        dst[0] = make_int4(v[0], v[1], v[2], v[3]);
        dst[1] = make_int4(v[4], v[5], v[6], v[7]);
    }
}

// ---------------------------------------------------------------------------
// Kernel 2: cooperative gather, 4 lanes/point, 8 points/warp, 64 pts/block.
//   Lane j: one 8B cell load (corners 2j, 2j+1) + 16B chunk j of each row.
//   Epilogue: conflict-free [channel][point] smem stage -> LDS.128/STG.128.
// ---------------------------------------------------------------------------
__global__ void __launch_bounds__(256)
octree_trilinear_coop4(const float4* __restrict__ pts,
                       float*        __restrict__ out,
                       int N, int G)
{
    __shared__ float sm[32][68];     // [channel][point], stride 68 (16B-aligned)

    const int tid    = threadIdx.x;
    const int warpId = tid >> 5;
    const int lane   = tid & 31;
    const int g      = lane >> 2;    // point-in-warp 0..7
    const int j      = lane & 3;     // chunk / corner-pair id 0..3

    const int n0     = blockIdx.x * 64;
    const int pLocal = warpId * 8 + g;            // 0..63
    const int p      = n0 + pLocal;
    const int pc     = (p < N) ? p : (N - 1);

    // --- geometry (4x redundant per point) ---
    const float4 q = pts[pc];
    const float xf = q.x - 0.5f, yf = q.y - 0.5f, zf = q.z - 0.5f;
    const float xi = floorf(xf), yi = floorf(yf), zi = floorf(zf);
    const float fx = xf - xi, fy = yf - yi, fz = zf - zi;
    const int GG = G + 1;
    const int ix = min(max((int)xi, -1), G - 1);
    const int iy = min(max((int)yi, -1), G - 1);
    const int iz = min(max((int)zi, -1), G - 1);

    // --- one 8B load: corners 2j (kz=0) and 2j+1 (kz=1) ---
    const int cid = ((ix + 1) * GG + (iy + 1)) * GG + (iz + 1);
    const int2 pr = __ldg(&reinterpret_cast<const int2*>(g_cell)[(size_t)cid * 4 + j]);
    int idxa = pr.x, idxb = pr.y;

    const float wxy = ((j & 2) ? fx : (1.0f - fx)) * ((j & 1) ? fy : (1.0f - fy));
    float wa = 0.0f, wb = 0.0f;
    if (idxa >= 0) wa = wxy * (1.0f - fz); else idxa = 0;
    if (idxb >= 0) wb = wxy * fz;          else idxb = 0;

    // --- broadcast all 8 (w, idx) across the 4-lane group ---
    float wk[8];
    int   rk[8];
#pragma unroll
    for (int k = 0; k < 4; ++k) {
        wk[2 * k]     = __shfl_sync(0xffffffffu, wa,   k, 4);
        wk[2 * k + 1] = __shfl_sync(0xffffffffu, wb,   k, 4);
        rk[2 * k]     = __shfl_sync(0xffffffffu, idxa, k, 4);
        rk[2 * k + 1] = __shfl_sync(0xffffffffu, idxb, k, 4);
    }

    float wsum = 0.0f;
#pragma unroll
    for (int k = 0; k < 8; ++k) wsum += wk[k];

    // --- gather: unconditional LDG.128, software-pipelined ---
    const uint4* __restrict__ feat16 = reinterpret_cast<const uint4*>(g_feat_h);

    float2 acc[4];                   // acc[u] = channels (2j+8u, 2j+8u+1)
#pragma unroll
    for (int u = 0; u < 4; ++u) acc[u] = make_float2(0.f, 0.f);

#define LDROW(k) __ldg(&feat16[(size_t)rk[k] * 4 + j])
#define CONSUME(v, w)                                                    \
    do {                                                                 \
        const __half2* hp = reinterpret_cast<const __half2*>(&(v));      \
        _Pragma("unroll")                                                \
        for (int u = 0; u < 4; ++u) {                                    \
            const float2 f = __half22float2(hp[u]);                      \
            acc[u].x = fmaf((w), f.x, acc[u].x);                         \
            acc[u].y = fmaf((w), f.y, acc[u].y);                         \
        }                                                                \
    } while (0)

    uint4 v0 = LDROW(0);
    uint4 v1 = LDROW(1);
    uint4 v2 = LDROW(2);
    uint4 v3 = LDROW(3);
    uint4 v4 = LDROW(4); CONSUME(v0, wk[0]);
    uint4 v5 = LDROW(5); CONSUME(v1, wk[1]);
    uint4 v6 = LDROW(6); CONSUME(v2, wk[2]);
    uint4 v7 = LDROW(7); CONSUME(v3, wk[3]);
    CONSUME(v4, wk[4]);
    CONSUME(v5, wk[5]);
    CONSUME(v6, wk[6]);
    CONSUME(v7, wk[7]);
#undef LDROW
#undef CONSUME

    const float inv = 1.0f / (wsum + 1e-10f);

    // --- stage: sm[channel][point]; conflict-free (bank = 8j+8w+g+{0,4}) ---
#pragma unroll
    for (int u = 0; u < 4; ++u) {
        sm[2 * j + 8 * u][pLocal]     = acc[u].x * inv;
        sm[2 * j + 8 * u + 1][pLocal] = acc[u].y * inv;
    }
    __syncthreads();

    // --- vectorized (C, N) store ---
    if ((n0 + 64 <= N) && ((N & 3) == 0)) {
#pragma unroll
        for (int r = 0; r < 2; ++r) {
            const int e  = r * 256 + tid;     // 0..511
            const int c  = e >> 4;            // channel 0..31
            const int u4 = e & 15;            // float4 slot (points 4u4..4u4+3)
            const float4 val = *reinterpret_cast<const float4*>(&sm[c][4 * u4]);
            *reinterpret_cast<float4*>(&out[(size_t)c * N + n0 + 4 * u4]) = val;
        }
    } else {
#pragma unroll
        for (int r = 0; r < 8; ++r) {
            const int e = r * 256 + tid;      // 0..2047
            const int c = e >> 6;             // channel
            const int i = e & 63;             // point-in-block
            if (n0 + i < N)
                out[(size_t)c * N + (n0 + i)] = sm[c][i];
        }
    }
}

// ---------------------------------------------------------------------------
// Launch. Inputs: data (f32), pts (f32), lut (i32), depth.
// ---------------------------------------------------------------------------
extern "C" void kernel_launch(void* const* d_in, const int* in_sizes, int n_in,
                              void* d_out, int out_size)
{
    const float* data = (const float*)d_in[0];
    const float* pts  = (const float*)d_in[1];
    const int*   lut  = (const int*)d_in[2];
    float*       out  = (float*)d_out;

    int G = 1;
    while (G * G * G < in_sizes[2]) G <<= 1;
    const int H = in_sizes[0] / NUM_C;
    const int N = in_sizes[1] / 4;

    {
        const int GG = G + 1;
        const int totalCells = GG * GG * GG;
        const int nTrans = (H + 63) / 64;
        const int nBuild = (totalCells + 255) / 256;
        prep_kernel<<<nTrans + nBuild, 256>>>(data, lut, H, G, nTrans);
    }
    {
        const int blocks = (N + 63) / 64;   // 64 points per 256-thread block
        octree_trilinear_coop4<<<blocks, 256>>>(
            (const float4*)pts, out, N, G);
    }
}